// round 11
// baseline (speedup 1.0000x reference)
#include <cuda_runtime.h>
#include <cstdint>

#define DIN  32
#define DOUT 32
#define TPB  192                            // 6 warps/block
#define NWARP (TPB / 32)
#define RPT  2                              // rows per thread (X = 64 regs)
#define TILE_ROWS (32 * RPT)                // 64 rows per warp-tile
#define STRIDE_F  36                        // padded smem row stride (floats)
#define TILE_FLOATS (TILE_ROWS * STRIDE_F)  // 2304 floats = 9216 B per buffer
#define NBUF 2                              // double-buffered prefetch
#define SMEM_BYTES (NWARP * NBUF * TILE_FLOATS * 4)   // 110592 B -> 2 blocks/SM

// W in constant memory: const port broadcasts uniform reads off the L1 crossbar
// (proven in round 10: L1 84% -> 52%, dur 650 -> 345 us).
__constant__ __align__(16) float Wc[DOUT * DIN];

// Packed 2-wide fp32 FMA / ADD (Blackwell f32x2 pipe; PTX-only).
__device__ __forceinline__ unsigned long long fma2(unsigned long long a,
                                                   unsigned long long b,
                                                   unsigned long long c) {
    unsigned long long d;
    asm("fma.rn.f32x2 %0, %1, %2, %3;" : "=l"(d) : "l"(a), "l"(b), "l"(c));
    return d;
}
__device__ __forceinline__ unsigned long long add2(unsigned long long a,
                                                   unsigned long long b) {
    unsigned long long d;
    asm("add.rn.f32x2 %0, %1, %2;" : "=l"(d) : "l"(a), "l"(b));
    return d;
}

union U64F2 { unsigned long long u; float2 f; };

__device__ __forceinline__ uint32_t smem_u32(const void* p) {
    return (uint32_t)__cvta_generic_to_shared(p);
}

// Prefetch one 64-row x-tile (16 KB) into a warp-private smem buffer via
// cp.async (no register cost, fully coalesced 16B/lane).
__device__ __forceinline__ void prefetch_tile(const float4* __restrict__ gx,
                                              float* buf, int lane) {
    #pragma unroll
    for (int i = 0; i < 16; ++i) {
        const int idx = i * 32 + lane;            // float4 chunk 0..511
        const int r = idx >> 3, c = idx & 7;
        uint32_t dst = smem_u32(&buf[r * STRIDE_F + c * 4]);
        asm volatile("cp.async.cg.shared.global [%0], [%1], 16;"
                     :: "r"(dst), "l"(gx + idx));
    }
}

extern "C" __global__ void __launch_bounds__(TPB, 2)
layer_relu_kernel(const float* __restrict__ x,
                  float* __restrict__ out,
                  int nrows)
{
    extern __shared__ float smem[];
    const int lane = threadIdx.x & 31;
    const int wid  = threadIdx.x >> 5;
    float* buf[NBUF];
    buf[0] = smem + wid * NBUF * TILE_FLOATS;   // warp-private double buffer
    buf[1] = buf[0] + TILE_FLOATS;

    const int gwarp  = blockIdx.x * NWARP + wid;
    const int nwarps = gridDim.x * NWARP;
    const int ntiles = nrows / TILE_ROWS;

    // ---- Prologue: prefetch first tile
    if (gwarp < ntiles) {
        prefetch_tile(reinterpret_cast<const float4*>(
                          x + (long long)gwarp * TILE_ROWS * DIN),
                      buf[0], lane);
    }
    asm volatile("cp.async.commit_group;");

    int it = 0;
    for (int t = gwarp; t < ntiles; t += nwarps, ++it) {
        // ---- Prefetch next tile into the other buffer, then wait for current
        const int nt = t + nwarps;
        if (nt < ntiles) {
            prefetch_tile(reinterpret_cast<const float4*>(
                              x + (long long)nt * TILE_ROWS * DIN),
                          buf[(it + 1) & 1], lane);
        }
        asm volatile("cp.async.commit_group;");
        asm volatile("cp.async.wait_group 1;");   // tile t's group complete
        __syncwarp();
        float* tile = buf[it & 1];

        // ---- Step 2: per-thread rows (lane, lane+32) -> registers
        unsigned long long X[RPT][16];
        #pragma unroll
        for (int rr = 0; rr < RPT; ++rr) {
            const int r = lane + 32 * rr;
            #pragma unroll
            for (int j = 0; j < 8; ++j) {
                ulonglong2 v = *reinterpret_cast<const ulonglong2*>(
                    &tile[r * STRIDE_F + j * 4]);
                X[rr][2 * j]     = v.x;
                X[rr][2 * j + 1] = v.y;
            }
        }
        __syncwarp();   // x-tile dead; results will overwrite it

        // ---- Step 3: compute. W from __constant__; horizontal adds paired
        //      across output pairs via one add.f32x2 (fma-pipe saving).
        #pragma unroll
        for (int og = 0; og < 8; ++og) {
            float res[RPT][4];
            #pragma unroll
            for (int cp = 0; cp < 2; ++cp) {           // output pairs
                const int o0 = og * 4 + cp * 2;
                const ulonglong2* w0 =
                    reinterpret_cast<const ulonglong2*>(&Wc[o0 * DIN]);
                const ulonglong2* w1 =
                    reinterpret_cast<const ulonglong2*>(&Wc[(o0 + 1) * DIN]);
                #pragma unroll
                for (int rr = 0; rr < RPT; ++rr) {
                    unsigned long long a0 = 0ull, a1 = 0ull;
                    #pragma unroll
                    for (int j = 0; j < 8; ++j) {
                        const ulonglong2 wa = w0[j];
                        const ulonglong2 wb = w1[j];
                        a0 = fma2(X[rr][2 * j],     wa.x, a0);
                        a0 = fma2(X[rr][2 * j + 1], wa.y, a0);
                        a1 = fma2(X[rr][2 * j],     wb.x, a1);
                        a1 = fma2(X[rr][2 * j + 1], wb.y, a1);
                    }
                    // {a0.x, a1.x} + {a0.y, a1.y} = {sum0, sum1} in one add2
                    U64F2 u0, u1, plo, phi, s;
                    u0.u = a0; u1.u = a1;
                    plo.f = make_float2(u0.f.x, u1.f.x);
                    phi.f = make_float2(u0.f.y, u1.f.y);
                    s.u = add2(plo.u, phi.u);
                    res[rr][cp * 2]     = fmaxf(s.f.x, 0.0f);  // alu-pipe relu
                    res[rr][cp * 2 + 1] = fmaxf(s.f.y, 0.0f);
                }
            }
            #pragma unroll
            for (int rr = 0; rr < RPT; ++rr) {
                const int r = lane + 32 * rr;
                *reinterpret_cast<float4*>(&tile[r * STRIDE_F + og * 4]) =
                    make_float4(res[rr][0], res[rr][1], res[rr][2], res[rr][3]);
            }
        }
        __syncwarp();

        // ---- Step 4: coalesced smem -> gmem out
        {
            float4* gout = reinterpret_cast<float4*>(
                out + (long long)t * TILE_ROWS * DOUT);
            #pragma unroll
            for (int i = 0; i < 16; ++i) {
                const int idx = i * 32 + lane;
                const int r = idx >> 3, c = idx & 7;
                gout[idx] = *reinterpret_cast<const float4*>(
                    &tile[r * STRIDE_F + c * 4]);
            }
        }
        __syncwarp();   // all lanes' reads done before next prefetch reuses buf
    }

    // ---- Tail: leftover rows (< TILE_ROWS); never taken for N=8388608
    const long long tailBase = (long long)ntiles * TILE_ROWS;
    if (tailBase < nrows && gwarp == 0) {
        for (long long r = tailBase + lane; r < nrows; r += 32) {
            float xv[DIN];
            #pragma unroll
            for (int k = 0; k < DIN; ++k) xv[k] = x[r * DIN + k];
            #pragma unroll
            for (int o = 0; o < DOUT; ++o) {
                float s = 0.f;
                #pragma unroll
                for (int k = 0; k < DIN; ++k)
                    s = fmaf(xv[k], Wc[o * DIN + k], s);
                out[r * DOUT + o] = fmaxf(s, 0.f);
            }
        }
    }
}

extern "C" void kernel_launch(void* const* d_in, const int* in_sizes, int n_in,
                              void* d_out, int out_size) {
    const float* x = (const float*)d_in[0];   // [N, 32] fp32
    const float* W = (const float*)d_in[1];   // [32, 32] fp32
    float* out     = (float*)d_out;           // [N, 32] fp32

    const int nrows = in_sizes[0] / DIN;      // 8388608

    cudaFuncSetAttribute(layer_relu_kernel,
                         cudaFuncAttributeMaxDynamicSharedMemorySize, SMEM_BYTES);

    // Device-to-device copy into the constant bank; captures as a memcpy node.
    cudaMemcpyToSymbolAsync(Wc, W, DOUT * DIN * sizeof(float), 0,
                            cudaMemcpyDeviceToDevice, 0);

    const int blocks = 4096;                  // grid-stride over 131072 tiles
    layer_relu_kernel<<<blocks, TPB, SMEM_BYTES>>>(x, out, nrows);
}

// round 12
// speedup vs baseline: 1.0032x; 1.0032x over previous
#include <cuda_runtime.h>
#include <cstdint>

#define DIN  32
#define DOUT 32
#define TPB  192                            // 6 warps/block
#define NWARP (TPB / 32)
#define RPT  2                              // rows per thread (X = 64 regs)
#define TILE_ROWS (32 * RPT)                // 64 rows per warp-tile
#define STRIDE_F  36                        // padded smem row stride (floats)
#define TILE_FLOATS (TILE_ROWS * STRIDE_F)  // 2304 floats = 9216 B per buffer
#define NBUF 2                              // double-buffered prefetch
#define SMEM_BYTES (NWARP * NBUF * TILE_FLOATS * 4)   // 110592 B -> 2 blocks/SM

// W in constant memory: const port broadcasts uniform reads off the L1 crossbar
// (proven in round 10: L1 84% -> 52%, dur 650 -> 345 us).
__constant__ __align__(16) float Wc[DOUT * DIN];

// Packed 2-wide fp32 FMA / ADD (Blackwell f32x2 pipe; PTX-only).
__device__ __forceinline__ unsigned long long fma2(unsigned long long a,
                                                   unsigned long long b,
                                                   unsigned long long c) {
    unsigned long long d;
    asm("fma.rn.f32x2 %0, %1, %2, %3;" : "=l"(d) : "l"(a), "l"(b), "l"(c));
    return d;
}
__device__ __forceinline__ unsigned long long add2(unsigned long long a,
                                                   unsigned long long b) {
    unsigned long long d;
    asm("add.rn.f32x2 %0, %1, %2;" : "=l"(d) : "l"(a), "l"(b));
    return d;
}

union U64F2 { unsigned long long u; float2 f; };

__device__ __forceinline__ uint32_t smem_u32(const void* p) {
    return (uint32_t)__cvta_generic_to_shared(p);
}

// Prefetch one 64-row x-tile (16 KB) into a warp-private smem buffer via
// cp.async (no register cost, fully coalesced 16B/lane).
__device__ __forceinline__ void prefetch_tile(const float4* __restrict__ gx,
                                              float* buf, int lane) {
    #pragma unroll
    for (int i = 0; i < 16; ++i) {
        const int idx = i * 32 + lane;            // float4 chunk 0..511
        const int r = idx >> 3, c = idx & 7;
        uint32_t dst = smem_u32(&buf[r * STRIDE_F + c * 4]);
        asm volatile("cp.async.cg.shared.global [%0], [%1], 16;"
                     :: "r"(dst), "l"(gx + idx));
    }
}

extern "C" __global__ void __launch_bounds__(TPB, 2)
layer_relu_kernel(const float* __restrict__ x,
                  float* __restrict__ out,
                  int nrows)
{
    extern __shared__ float smem[];
    const int lane = threadIdx.x & 31;
    const int wid  = threadIdx.x >> 5;
    float* buf[NBUF];
    buf[0] = smem + wid * NBUF * TILE_FLOATS;   // warp-private double buffer
    buf[1] = buf[0] + TILE_FLOATS;

    const int gwarp  = blockIdx.x * NWARP + wid;
    const int nwarps = gridDim.x * NWARP;
    const int ntiles = nrows / TILE_ROWS;

    // ---- Prologue: prefetch first tile
    if (gwarp < ntiles) {
        prefetch_tile(reinterpret_cast<const float4*>(
                          x + (long long)gwarp * TILE_ROWS * DIN),
                      buf[0], lane);
    }
    asm volatile("cp.async.commit_group;");

    int it = 0;
    for (int t = gwarp; t < ntiles; t += nwarps, ++it) {
        // ---- Prefetch next tile into the other buffer, then wait for current
        const int nt = t + nwarps;
        if (nt < ntiles) {
            prefetch_tile(reinterpret_cast<const float4*>(
                              x + (long long)nt * TILE_ROWS * DIN),
                          buf[(it + 1) & 1], lane);
        }
        asm volatile("cp.async.commit_group;");
        asm volatile("cp.async.wait_group 1;");   // tile t's group complete
        __syncwarp();
        float* tile = buf[it & 1];

        // ---- Step 2: per-thread rows (lane, lane+32) -> registers
        unsigned long long X[RPT][16];
        #pragma unroll
        for (int rr = 0; rr < RPT; ++rr) {
            const int r = lane + 32 * rr;
            #pragma unroll
            for (int j = 0; j < 8; ++j) {
                ulonglong2 v = *reinterpret_cast<const ulonglong2*>(
                    &tile[r * STRIDE_F + j * 4]);
                X[rr][2 * j]     = v.x;
                X[rr][2 * j + 1] = v.y;
            }
        }
        __syncwarp();   // x-tile dead; results will overwrite it

        // ---- Step 3: compute. W from __constant__; horizontal adds paired
        //      across output pairs via one add.f32x2 (fma-pipe saving).
        #pragma unroll
        for (int og = 0; og < 8; ++og) {
            float res[RPT][4];
            #pragma unroll
            for (int cp = 0; cp < 2; ++cp) {           // output pairs
                const int o0 = og * 4 + cp * 2;
                const ulonglong2* w0 =
                    reinterpret_cast<const ulonglong2*>(&Wc[o0 * DIN]);
                const ulonglong2* w1 =
                    reinterpret_cast<const ulonglong2*>(&Wc[(o0 + 1) * DIN]);
                #pragma unroll
                for (int rr = 0; rr < RPT; ++rr) {
                    unsigned long long a0 = 0ull, a1 = 0ull;
                    #pragma unroll
                    for (int j = 0; j < 8; ++j) {
                        const ulonglong2 wa = w0[j];
                        const ulonglong2 wb = w1[j];
                        a0 = fma2(X[rr][2 * j],     wa.x, a0);
                        a0 = fma2(X[rr][2 * j + 1], wa.y, a0);
                        a1 = fma2(X[rr][2 * j],     wb.x, a1);
                        a1 = fma2(X[rr][2 * j + 1], wb.y, a1);
                    }
                    // {a0.x, a1.x} + {a0.y, a1.y} = {sum0, sum1} in one add2
                    U64F2 u0, u1, plo, phi, s;
                    u0.u = a0; u1.u = a1;
                    plo.f = make_float2(u0.f.x, u1.f.x);
                    phi.f = make_float2(u0.f.y, u1.f.y);
                    s.u = add2(plo.u, phi.u);
                    res[rr][cp * 2]     = fmaxf(s.f.x, 0.0f);  // alu-pipe relu
                    res[rr][cp * 2 + 1] = fmaxf(s.f.y, 0.0f);
                }
            }
            #pragma unroll
            for (int rr = 0; rr < RPT; ++rr) {
                const int r = lane + 32 * rr;
                *reinterpret_cast<float4*>(&tile[r * STRIDE_F + og * 4]) =
                    make_float4(res[rr][0], res[rr][1], res[rr][2], res[rr][3]);
            }
        }
        __syncwarp();

        // ---- Step 4: coalesced smem -> gmem out
        {
            float4* gout = reinterpret_cast<float4*>(
                out + (long long)t * TILE_ROWS * DOUT);
            #pragma unroll
            for (int i = 0; i < 16; ++i) {
                const int idx = i * 32 + lane;
                const int r = idx >> 3, c = idx & 7;
                gout[idx] = *reinterpret_cast<const float4*>(
                    &tile[r * STRIDE_F + c * 4]);
            }
        }
        __syncwarp();   // all lanes' reads done before next prefetch reuses buf
    }

    // ---- Tail: leftover rows (< TILE_ROWS); never taken for N=8388608
    const long long tailBase = (long long)ntiles * TILE_ROWS;
    if (tailBase < nrows && gwarp == 0) {
        for (long long r = tailBase + lane; r < nrows; r += 32) {
            float xv[DIN];
            #pragma unroll
            for (int k = 0; k < DIN; ++k) xv[k] = x[r * DIN + k];
            #pragma unroll
            for (int o = 0; o < DOUT; ++o) {
                float s = 0.f;
                #pragma unroll
                for (int k = 0; k < DIN; ++k)
                    s = fmaf(xv[k], Wc[o * DIN + k], s);
                out[r * DOUT + o] = fmaxf(s, 0.f);
            }
        }
    }
}

extern "C" void kernel_launch(void* const* d_in, const int* in_sizes, int n_in,
                              void* d_out, int out_size) {
    const float* x = (const float*)d_in[0];   // [N, 32] fp32
    const float* W = (const float*)d_in[1];   // [32, 32] fp32
    float* out     = (float*)d_out;           // [N, 32] fp32

    const int nrows = in_sizes[0] / DIN;      // 8388608

    cudaFuncSetAttribute(layer_relu_kernel,
                         cudaFuncAttributeMaxDynamicSharedMemorySize, SMEM_BYTES);

    // Device-to-device copy into the constant bank; captures as a memcpy node.
    cudaMemcpyToSymbolAsync(Wc, W, DOUT * DIN * sizeof(float), 0,
                            cudaMemcpyDeviceToDevice, 0);

    const int blocks = 4096;                  // grid-stride over 131072 tiles
    layer_relu_kernel<<<blocks, TPB, SMEM_BYTES>>>(x, out, nrows);
}

// round 13
// speedup vs baseline: 1.1625x; 1.1588x over previous
#include <cuda_runtime.h>
#include <cstdint>

#define DIN  32
#define DOUT 32
#define TPB  256
#define NWARP (TPB / 32)
#define RPT  2                              // rows per thread (X = 64 regs)
#define TILE_ROWS (32 * RPT)                // 64 rows per warp-tile
#define STRIDE_F  36                        // padded smem row stride (floats)
#define TILE_FLOATS (TILE_ROWS * STRIDE_F)  // 2304 floats = 9216 B per warp
#define SMEM_BYTES (NWARP * TILE_FLOATS * 4)  // 73728 B per block -> 2 blocks/SM

// W in constant memory: const port broadcasts uniform reads off the L1 crossbar
// (proven: L1 84% -> 52%, dur 650 -> 345 us in round 10).
__constant__ __align__(16) float Wc[DOUT * DIN];

// Packed 2-wide fp32 FMA (Blackwell f32x2 pipe; PTX-only).
__device__ __forceinline__ unsigned long long fma2(unsigned long long a,
                                                   unsigned long long b,
                                                   unsigned long long c) {
    unsigned long long d;
    asm("fma.rn.f32x2 %0, %1, %2, %3;" : "=l"(d) : "l"(a), "l"(b), "l"(c));
    return d;
}

union U64F2 { unsigned long long u; float2 f; };

extern "C" __global__ void __launch_bounds__(TPB, 2)
layer_relu_kernel(const float* __restrict__ x,
                  float* __restrict__ out,
                  int nrows)
{
    extern __shared__ float smem[];
    const int lane = threadIdx.x & 31;
    const int wid  = threadIdx.x >> 5;
    float* tile = smem + wid * TILE_FLOATS;   // warp-private tile

    const int gwarp  = blockIdx.x * NWARP + wid;
    const int nwarps = gridDim.x * NWARP;
    const int ntiles = nrows / TILE_ROWS;

    for (int t = gwarp; t < ntiles; t += nwarps) {
        const long long rowBase = (long long)t * TILE_ROWS;

        // ---- Step 1: coalesced gmem -> smem (64 rows x 128 B)
        {
            const float4* gx = reinterpret_cast<const float4*>(x + rowBase * DIN);
            #pragma unroll
            for (int i = 0; i < 16; ++i) {
                const int idx = i * 32 + lane;            // float4 chunk 0..511
                float4 v = __ldg(&gx[idx]);
                const int r = idx >> 3, c = idx & 7;
                *reinterpret_cast<float4*>(&tile[r * STRIDE_F + c * 4]) = v;
            }
        }

        // ---- Prefetch next tile's 16 KB into L2 (no regs, no smem, no sync):
        //      converts next iteration's exposed DRAM latency into L2 latency.
        {
            const int nt = t + nwarps;
            if (nt < ntiles) {
                const char* nb = reinterpret_cast<const char*>(
                    x + (long long)nt * TILE_ROWS * DIN);
                #pragma unroll
                for (int i = 0; i < 4; ++i) {
                    const char* p = nb + (i * 32 + lane) * 128;
                    asm volatile("prefetch.global.L2 [%0];" :: "l"(p));
                }
            }
        }
        __syncwarp();

        // ---- Step 2: per-thread rows (lane, lane+32) -> registers
        unsigned long long X[RPT][16];
        #pragma unroll
        for (int rr = 0; rr < RPT; ++rr) {
            const int r = lane + 32 * rr;
            #pragma unroll
            for (int j = 0; j < 8; ++j) {
                ulonglong2 v = *reinterpret_cast<const ulonglong2*>(
                    &tile[r * STRIDE_F + j * 4]);
                X[rr][2 * j]     = v.x;
                X[rr][2 * j + 1] = v.y;
            }
        }
        __syncwarp();   // x-tile dead; results will overwrite it

        // ---- Step 3: compute. W from __constant__ (const port broadcast)
        #pragma unroll
        for (int og = 0; og < 8; ++og) {
            float res[RPT][4];
            #pragma unroll
            for (int c = 0; c < 4; ++c) {
                const int o = og * 4 + c;
                const ulonglong2* wr =
                    reinterpret_cast<const ulonglong2*>(&Wc[o * DIN]);
                #pragma unroll
                for (int rr = 0; rr < RPT; ++rr) {
                    unsigned long long acc = 0ull;
                    #pragma unroll
                    for (int j = 0; j < 8; ++j) {
                        const ulonglong2 w = wr[j];
                        acc = fma2(X[rr][2 * j],     w.x, acc);
                        acc = fma2(X[rr][2 * j + 1], w.y, acc);
                    }
                    U64F2 u; u.u = acc;
                    res[rr][c] = fmaxf(u.f.x + u.f.y, 0.0f);
                }
            }
            #pragma unroll
            for (int rr = 0; rr < RPT; ++rr) {
                const int r = lane + 32 * rr;
                *reinterpret_cast<float4*>(&tile[r * STRIDE_F + og * 4]) =
                    make_float4(res[rr][0], res[rr][1], res[rr][2], res[rr][3]);
            }
        }
        __syncwarp();

        // ---- Step 4: coalesced smem -> gmem, streaming stores (evict-first:
        //      out is write-once, keep L2 for the x-read stream)
        {
            float4* gout = reinterpret_cast<float4*>(out + rowBase * DOUT);
            #pragma unroll
            for (int i = 0; i < 16; ++i) {
                const int idx = i * 32 + lane;
                const int r = idx >> 3, c = idx & 7;
                __stcs(&gout[idx], *reinterpret_cast<const float4*>(
                                       &tile[r * STRIDE_F + c * 4]));
            }
        }
        __syncwarp();
    }

    // ---- Tail: leftover rows (< TILE_ROWS); never taken for N=8388608
    const long long tailBase = (long long)ntiles * TILE_ROWS;
    if (tailBase < nrows && gwarp == 0) {
        for (long long r = tailBase + lane; r < nrows; r += 32) {
            float xv[DIN];
            #pragma unroll
            for (int k = 0; k < DIN; ++k) xv[k] = x[r * DIN + k];
            #pragma unroll
            for (int o = 0; o < DOUT; ++o) {
                float s = 0.f;
                #pragma unroll
                for (int k = 0; k < DIN; ++k)
                    s = fmaf(xv[k], Wc[o * DIN + k], s);
                out[r * DOUT + o] = fmaxf(s, 0.f);
            }
        }
    }
}

extern "C" void kernel_launch(void* const* d_in, const int* in_sizes, int n_in,
                              void* d_out, int out_size) {
    const float* x = (const float*)d_in[0];   // [N, 32] fp32
    const float* W = (const float*)d_in[1];   // [32, 32] fp32
    float* out     = (float*)d_out;           // [N, 32] fp32

    const int nrows = in_sizes[0] / DIN;      // 8388608

    cudaFuncSetAttribute(layer_relu_kernel,
                         cudaFuncAttributeMaxDynamicSharedMemorySize, SMEM_BYTES);

    // Device-to-device copy into the constant bank; captures as a memcpy node.
    cudaMemcpyToSymbolAsync(Wc, W, DOUT * DIN * sizeof(float), 0,
                            cudaMemcpyDeviceToDevice, 0);

    const int blocks = 4096;                  // grid-stride over 131072 tiles
    layer_relu_kernel<<<blocks, TPB, SMEM_BYTES>>>(x, out, nrows);
}